// round 7
// baseline (speedup 1.0000x reference)
#include <cuda_runtime.h>
#include <cuda_bf16.h>

// Problem constants
#define BB   512
#define SS   1024
#define FIN  16      // features per (b,s); feature 15 is delta
#define HH   64
#define GG   192     // 3*H
#define NT   192     // scan: one thread per output column g, 1 batch per CTA
#define XROWS 64     // rows per x-projection block
#define NTP  192     // x-projection block threads

typedef unsigned long long u64;

// Device scratch (sanctioned alternative to cudaMalloc)
__device__ float g_xp[(size_t)BB * SS * GG];   // x-projection + input bias (402 MB)
__device__ float g_dm[BB];                     // T * mean(delta) per batch

// ---- packed f32x2 helpers (bit-exact fp32, 2 FMA per fma-pipe slot) ----
__device__ __forceinline__ u64 pack2(float lo, float hi) {
    u64 r; asm("mov.b64 %0, {%1, %2};" : "=l"(r) : "f"(lo), "f"(hi)); return r;
}
__device__ __forceinline__ void unpack2(u64 v, float& lo, float& hi) {
    asm("mov.b64 {%0, %1}, %2;" : "=f"(lo), "=f"(hi) : "l"(v));
}
__device__ __forceinline__ u64 fma2(u64 a, u64 b, u64 c) {
    u64 d; asm("fma.rn.f32x2 %0, %1, %2, %3;" : "=l"(d) : "l"(a), "l"(b), "l"(c)); return d;
}
__device__ __forceinline__ u64 add2(u64 a, u64 b) {
    u64 d; asm("add.rn.f32x2 %0, %1, %2;" : "=l"(d) : "l"(a), "l"(b)); return d;
}

__device__ __forceinline__ float sigmoidf_(float x) {
    return __fdividef(1.0f, 1.0f + __expf(-x));
}
__device__ __forceinline__ float tanhf_(float x) {
    return __fdividef(2.0f, 1.0f + __expf(-2.0f * x)) - 1.0f;
}

// ---------------- Kernel 1: per-batch delta mean * T ----------------
__global__ void dmean_kernel(const float* __restrict__ inputs,
                             const float* __restrict__ Tp) {
    __shared__ float red[256];
    const int b   = blockIdx.x;
    const int tid = threadIdx.x;
    float s = 0.0f;
    for (int i = tid; i < SS; i += 256)
        s += inputs[((size_t)b * SS + i) * FIN + 15];
    red[tid] = s;
    __syncthreads();
    for (int off = 128; off > 0; off >>= 1) {
        if (tid < off) red[tid] += red[tid + off];
        __syncthreads();
    }
    if (tid == 0) g_dm[b] = Tp[0] * red[0] * (1.0f / (float)SS);
}

// ---------------- Kernel 2: x-projection pre-pass ----------------
// g_xp[bs][g] = sum_{f<15} x[bs][f] * K[f][g] + bias_in[g]
__global__ __launch_bounds__(NTP)
void xproj_kernel(const float* __restrict__ inputs,
                  const float* __restrict__ k_in,
                  const float* __restrict__ bias) {
    __shared__ __align__(16) float sx[XROWS * FIN];
    const int g = threadIdx.x;
    const size_t row0 = (size_t)blockIdx.x * XROWS;

    u64 K2[8];
    #pragma unroll
    for (int f2 = 0; f2 < 8; f2++) {
        float lo = k_in[(2 * f2) * GG + g];
        float hi = (2 * f2 + 1 < 15) ? k_in[(2 * f2 + 1) * GG + g] : 0.0f;
        K2[f2] = pack2(lo, hi);
    }
    const float bi = bias[g];

    // stage 64 input rows (contiguous 4KB)
    const float4* src = (const float4*)(inputs + row0 * FIN);
    for (int i = g; i < XROWS * 4; i += NTP) ((float4*)sx)[i] = src[i];
    __syncthreads();

    float* dst = g_xp + row0 * GG + g;
    #pragma unroll 4
    for (int r = 0; r < XROWS; r++) {
        const ulonglong2* xr = (const ulonglong2*)(sx + r * FIN);
        ulonglong2 xv0 = xr[0], xv1 = xr[1];
        u64 c0 = fma2(xv0.x, K2[0], 0ull);
        u64 c1 = fma2(xv0.y, K2[1], 0ull);
        c0 = fma2(xv1.x, K2[2], c0);
        c1 = fma2(xv1.y, K2[3], c1);
        ulonglong2 xv2 = xr[2], xv3 = xr[3];
        c0 = fma2(xv2.x, K2[4], c0);
        c1 = fma2(xv2.y, K2[5], c1);
        c0 = fma2(xv3.x, K2[6], c0);
        c1 = fma2(xv3.y, K2[7], c1);
        float lo, hi; unpack2(add2(c0, c1), lo, hi);
        dst[(size_t)r * GG] = bi + (lo + hi);
    }
}

// ---------------- Kernel 3: GRU scan (recurrent part only) ----------------
__global__ __launch_bounds__(NT, 4)
void gru_scan_kernel(const float* __restrict__ r_in,     // (64,192)
                     const float* __restrict__ bias,     // (2,192)
                     const float* __restrict__ w1,       // (64,64)
                     const float* __restrict__ b1,       // (64)
                     const float* __restrict__ bn_gamma,
                     const float* __restrict__ bn_beta,
                     const float* __restrict__ bn_mean,
                     const float* __restrict__ bn_var,
                     const float* __restrict__ w2,       // (64,1)
                     const float* __restrict__ b2,       // (1)
                     float* __restrict__ out)            // (B,1)
{
    __shared__ __align__(16) float sm_h[HH];     // hidden state
    __shared__ __align__(16) float sm_s[256];    // [0:128)=z/r-pre ; [128:192)=xh ; [192:256)=rh
    __shared__ float sm_e[HH];

    const int g = threadIdx.x;                   // output column 0..191
    const int b = blockIdx.x;                    // batch

    // recurrent weights for column g, packed pairs over k
    u64 R2[32];
    #pragma unroll
    for (int k2 = 0; k2 < 32; k2++)
        R2[k2] = pack2(r_in[(2 * k2) * GG + g], r_in[(2 * k2 + 1) * GG + g]);
    const float br = bias[GG + g];

    if (g < HH) sm_h[g] = 0.0f;

    const float* xpp = g_xp + (size_t)b * SS * GG + g;
    float vx0 = xpp[0];
    float vx1 = xpp[GG];
    __syncthreads();

    for (int s = 0; s < SS; s++) {
        // prefetch x-projection two steps ahead (hides DRAM latency)
        float nx = 0.0f;
        if (s + 2 < SS) nx = xpp[(size_t)(s + 2) * GG];

        // recurrent dot: vr = h . R + br
        const ulonglong2* h4 = (const ulonglong2*)sm_h;   // LDS.128 broadcast
        u64 a0 = 0ull, a1 = 0ull;
        #pragma unroll
        for (int q = 0; q < 8; q++) {
            ulonglong2 hv0 = h4[2 * q];
            ulonglong2 hv1 = h4[2 * q + 1];
            a0 = fma2(hv0.x, R2[4 * q],     a0);
            a1 = fma2(hv0.y, R2[4 * q + 1], a1);
            a0 = fma2(hv1.x, R2[4 * q + 2], a0);
            a1 = fma2(hv1.y, R2[4 * q + 3], a1);
        }
        float r0, r1; unpack2(add2(a0, a1), r0, r1);
        const float vr = br + (r0 + r1);

        if (g < 128) {
            sm_s[g] = vx0 + vr;          // z-pre / r-pre (both biases folded in)
        } else {
            sm_s[g]      = vx0;          // xh (input bias folded in xp)
            sm_s[g + 64] = vr;           // rh
        }
        __syncthreads();

        if (g < HH) {
            float z  = sigmoidf_(sm_s[g]);
            float r  = sigmoidf_(sm_s[64 + g]);
            float hh = tanhf_(sm_s[128 + g] + r * sm_s[192 + g]);
            float ho = sm_h[g];
            sm_h[g] = z * (ho - hh) + hh;
        }
        vx0 = vx1;
        vx1 = nx;
        __syncthreads();
    }

    // ---------- Epilogue: delta effect + MLP head + BN ----------
    if (g < HH) {
        const float db  = g_dm[b];
        float acc = b1[g];
        #pragma unroll 8
        for (int k = 0; k < HH; k++)
            acc += (sm_h[k] + db) * w1[k * HH + g];
        float hr = fmaxf(acc, 0.0f);
        float hb = (hr - bn_mean[g]) * rsqrtf(bn_var[g] + 1e-3f) * bn_gamma[g] + bn_beta[g];
        sm_e[g] = hb * w2[g];
    }
    __syncthreads();

    if (g == 0) {
        float acc = b2[0];
        #pragma unroll 8
        for (int jj = 0; jj < HH; jj++) acc += sm_e[jj];
        out[b] = acc;
    }
}

extern "C" void kernel_launch(void* const* d_in, const int* in_sizes, int n_in,
                              void* d_out, int out_size) {
    const float* inputs   = (const float*)d_in[0];
    const float* gk       = (const float*)d_in[1];
    const float* grk      = (const float*)d_in[2];
    const float* gbias    = (const float*)d_in[3];
    const float* w1       = (const float*)d_in[4];
    const float* b1       = (const float*)d_in[5];
    const float* bn_gamma = (const float*)d_in[6];
    const float* bn_beta  = (const float*)d_in[7];
    const float* bn_mean  = (const float*)d_in[8];
    const float* bn_var   = (const float*)d_in[9];
    const float* w2       = (const float*)d_in[10];
    const float* b2       = (const float*)d_in[11];
    const float* T        = (const float*)d_in[12];
    float* out = (float*)d_out;

    dmean_kernel<<<BB, 256>>>(inputs, T);
    xproj_kernel<<<(BB * SS) / XROWS, NTP>>>(inputs, gk, gbias);
    gru_scan_kernel<<<BB, NT>>>(grk, gbias, w1, b1,
                                bn_gamma, bn_beta, bn_mean, bn_var,
                                w2, b2, out);
}

// round 8
// speedup vs baseline: 1.5269x; 1.5269x over previous
#include <cuda_runtime.h>
#include <cuda_bf16.h>

// Problem constants
#define BB   512
#define SS   1024
#define FIN  16      // features per (b,s); feature 15 is delta
#define HH   64
#define GG   192     // 3*H
#define XROWS 64     // rows per x-projection block
#define NTP  192     // x-projection block threads

typedef unsigned long long u64;

// Device scratch (sanctioned alternative to cudaMalloc)
__device__ float g_xp[(size_t)BB * SS * GG];   // x-projection + input bias (402 MB)
__device__ float g_dm[BB];                     // T * mean(delta) per batch

// ---- packed f32x2 helpers (bit-exact fp32, 2 FMA per fma-pipe slot) ----
__device__ __forceinline__ u64 pack2(float lo, float hi) {
    u64 r; asm("mov.b64 %0, {%1, %2};" : "=l"(r) : "f"(lo), "f"(hi)); return r;
}
__device__ __forceinline__ void unpack2(u64 v, float& lo, float& hi) {
    asm("mov.b64 {%0, %1}, %2;" : "=f"(lo), "=f"(hi) : "l"(v));
}
__device__ __forceinline__ u64 fma2(u64 a, u64 b, u64 c) {
    u64 d; asm("fma.rn.f32x2 %0, %1, %2, %3;" : "=l"(d) : "l"(a), "l"(b), "l"(c)); return d;
}
__device__ __forceinline__ u64 add2(u64 a, u64 b) {
    u64 d; asm("add.rn.f32x2 %0, %1, %2;" : "=l"(d) : "l"(a), "l"(b)); return d;
}
__device__ __forceinline__ float tanh_fast(float x) {
    float t; asm("tanh.approx.f32 %0, %1;" : "=f"(t) : "f"(x)); return t;
}

// ---------------- Kernel 1: per-batch delta mean * T ----------------
__global__ void dmean_kernel(const float* __restrict__ inputs,
                             const float* __restrict__ Tp) {
    __shared__ float red[256];
    const int b   = blockIdx.x;
    const int tid = threadIdx.x;
    float s = 0.0f;
    for (int i = tid; i < SS; i += 256)
        s += inputs[((size_t)b * SS + i) * FIN + 15];
    red[tid] = s;
    __syncthreads();
    for (int off = 128; off > 0; off >>= 1) {
        if (tid < off) red[tid] += red[tid + off];
        __syncthreads();
    }
    if (tid == 0) g_dm[b] = Tp[0] * red[0] * (1.0f / (float)SS);
}

// ---------------- Kernel 2: x-projection pre-pass ----------------
// g_xp[bs][g] = sum_{f<15} x[bs][f] * K[f][g] + bias_in[g]
__global__ __launch_bounds__(NTP)
void xproj_kernel(const float* __restrict__ inputs,
                  const float* __restrict__ k_in,
                  const float* __restrict__ bias) {
    __shared__ __align__(16) float sx[XROWS * FIN];
    const int g = threadIdx.x;
    const size_t row0 = (size_t)blockIdx.x * XROWS;

    u64 K2[8];
    #pragma unroll
    for (int f2 = 0; f2 < 8; f2++) {
        float lo = k_in[(2 * f2) * GG + g];
        float hi = (2 * f2 + 1 < 15) ? k_in[(2 * f2 + 1) * GG + g] : 0.0f;
        K2[f2] = pack2(lo, hi);
    }
    const float bi = bias[g];

    const float4* src = (const float4*)(inputs + row0 * FIN);
    for (int i = g; i < XROWS * 4; i += NTP) ((float4*)sx)[i] = src[i];
    __syncthreads();

    float* dst = g_xp + row0 * GG + g;
    #pragma unroll 4
    for (int r = 0; r < XROWS; r++) {
        const ulonglong2* xr = (const ulonglong2*)(sx + r * FIN);
        ulonglong2 xv0 = xr[0], xv1 = xr[1];
        u64 c0 = fma2(xv0.x, K2[0], 0ull);
        u64 c1 = fma2(xv0.y, K2[1], 0ull);
        c0 = fma2(xv1.x, K2[2], c0);
        c1 = fma2(xv1.y, K2[3], c1);
        ulonglong2 xv2 = xr[2], xv3 = xr[3];
        c0 = fma2(xv2.x, K2[4], c0);
        c1 = fma2(xv2.y, K2[5], c1);
        c0 = fma2(xv3.x, K2[6], c0);
        c1 = fma2(xv3.y, K2[7], c1);
        float lo, hi; unpack2(add2(c0, c1), lo, hi);
        dst[(size_t)r * GG] = bi + (lo + hi);
    }
}

// ---------------- Kernel 3: GRU scan — one thread per column triple ----------------
__global__ __launch_bounds__(HH, 4)
void gru_scan_kernel(const float* __restrict__ r_in,     // (64,192)
                     const float* __restrict__ bias,     // (2,192)
                     const float* __restrict__ w1,       // (64,64)
                     const float* __restrict__ b1,       // (64)
                     const float* __restrict__ bn_gamma,
                     const float* __restrict__ bn_beta,
                     const float* __restrict__ bn_mean,
                     const float* __restrict__ bn_var,
                     const float* __restrict__ w2,       // (64,1)
                     const float* __restrict__ b2,       // (1)
                     float* __restrict__ out)            // (B,1)
{
    __shared__ __align__(16) float sm_h[2][HH];   // double-buffered hidden state
    __shared__ float sm_e[HH];

    const int j = threadIdx.x;    // column triple 0..63
    const int b = blockIdx.x;     // batch

    // Recurrent weights for columns j (z), 64+j (r), 128+j (h); f32x2 pairs over k
    u64 Rz[32], Rr[32], Rh[32];
    #pragma unroll
    for (int k2 = 0; k2 < 32; k2++) {
        Rz[k2] = pack2(r_in[(2 * k2) * GG + j],        r_in[(2 * k2 + 1) * GG + j]);
        Rr[k2] = pack2(r_in[(2 * k2) * GG + 64 + j],   r_in[(2 * k2 + 1) * GG + 64 + j]);
        Rh[k2] = pack2(r_in[(2 * k2) * GG + 128 + j],  r_in[(2 * k2 + 1) * GG + 128 + j]);
    }
    const float bz  = bias[GG + j];
    const float brr = bias[GG + 64 + j];
    const float brh = bias[GG + 128 + j];

    sm_h[0][j] = 0.0f;

    const float* xpp = g_xp + (size_t)b * SS * GG;
    // prefetch x-projection for s=0,1 (input bias already folded in)
    float xz0 = xpp[j],      xr0 = xpp[64 + j],      xh0 = xpp[128 + j];
    float xz1 = xpp[GG + j], xr1 = xpp[GG + 64 + j], xh1 = xpp[GG + 128 + j];
    __syncthreads();

    for (int s = 0; s < SS; s++) {
        const int p = s & 1;

        // prefetch s+2 (hides DRAM latency behind ~2 steps of compute)
        float xz2 = 0.f, xr2 = 0.f, xh2 = 0.f;
        if (s + 2 < SS) {
            const float* q = xpp + (size_t)(s + 2) * GG;
            xz2 = q[j]; xr2 = q[64 + j]; xh2 = q[128 + j];
        }

        // three recurrent dots, all in-thread (96 fma2, 6 chains of depth 16)
        const ulonglong2* h4 = (const ulonglong2*)sm_h[p];   // broadcast LDS.128
        u64 az0 = 0ull, az1 = 0ull, ar0 = 0ull, ar1 = 0ull, ah0 = 0ull, ah1 = 0ull;
        #pragma unroll
        for (int q2 = 0; q2 < 16; q2++) {
            ulonglong2 hv = h4[q2];
            az0 = fma2(hv.x, Rz[2 * q2],     az0);
            ar0 = fma2(hv.x, Rr[2 * q2],     ar0);
            ah0 = fma2(hv.x, Rh[2 * q2],     ah0);
            az1 = fma2(hv.y, Rz[2 * q2 + 1], az1);
            ar1 = fma2(hv.y, Rr[2 * q2 + 1], ar1);
            ah1 = fma2(hv.y, Rh[2 * q2 + 1], ah1);
        }
        float lo, hi;
        unpack2(add2(az0, az1), lo, hi);  const float az  = xz0 + bz  + (lo + hi);
        unpack2(add2(ar0, ar1), lo, hi);  const float ar_ = xr0 + brr + (lo + hi);
        unpack2(add2(ah0, ah1), lo, hi);  const float rh_ = brh + (lo + hi);

        // gates via MUFU.TANH (sigmoid(x) = 0.5 + 0.5*tanh(x/2))
        const float z  = 0.5f + 0.5f * tanh_fast(0.5f * az);
        const float r  = 0.5f + 0.5f * tanh_fast(0.5f * ar_);
        const float hh = tanh_fast(xh0 + r * rh_);
        const float ho = sm_h[p][j];
        sm_h[p ^ 1][j] = z * (ho - hh) + hh;

        xz0 = xz1; xr0 = xr1; xh0 = xh1;
        xz1 = xz2; xr1 = xr2; xh1 = xh2;
        __syncthreads();   // the ONLY barrier per step
    }

    // final h is in buffer 0 (SS even)
    const float* hf = sm_h[0];

    // ---------- Epilogue: delta effect + MLP head + BN ----------
    {
        const float db  = g_dm[b];
        float acc = b1[j];
        #pragma unroll 8
        for (int k = 0; k < HH; k++)
            acc += (hf[k] + db) * w1[k * HH + j];
        float hr = fmaxf(acc, 0.0f);
        float hb = (hr - bn_mean[j]) * rsqrtf(bn_var[j] + 1e-3f) * bn_gamma[j] + bn_beta[j];
        sm_e[j] = hb * w2[j];
    }
    __syncthreads();

    if (j == 0) {
        float acc = b2[0];
        #pragma unroll 8
        for (int k = 0; k < HH; k++) acc += sm_e[k];
        out[b] = acc;
    }
}

extern "C" void kernel_launch(void* const* d_in, const int* in_sizes, int n_in,
                              void* d_out, int out_size) {
    const float* inputs   = (const float*)d_in[0];
    const float* gk       = (const float*)d_in[1];
    const float* grk      = (const float*)d_in[2];
    const float* gbias    = (const float*)d_in[3];
    const float* w1       = (const float*)d_in[4];
    const float* b1       = (const float*)d_in[5];
    const float* bn_gamma = (const float*)d_in[6];
    const float* bn_beta  = (const float*)d_in[7];
    const float* bn_mean  = (const float*)d_in[8];
    const float* bn_var   = (const float*)d_in[9];
    const float* w2       = (const float*)d_in[10];
    const float* b2       = (const float*)d_in[11];
    const float* T        = (const float*)d_in[12];
    float* out = (float*)d_out;

    dmean_kernel<<<BB, 256>>>(inputs, T);
    xproj_kernel<<<(BB * SS) / XROWS, NTP>>>(inputs, gk, gbias);
    gru_scan_kernel<<<BB, HH>>>(grk, gbias, w1, b1,
                                bn_gamma, bn_beta, bn_mean, bn_var,
                                w2, b2, out);
}

// round 9
// speedup vs baseline: 1.5284x; 1.0010x over previous
#include <cuda_runtime.h>
#include <cuda_bf16.h>
#include <cuda_fp16.h>

// Problem constants
#define BB   512
#define SS   1024
#define SSP  (SS + 2)  // padded rows per batch (prefetch overrun)
#define FIN  16        // features per (b,s); feature 15 is delta
#define HH   64
#define GG   192       // 3*H
#define XROWS 64       // rows per x-projection block
#define NTP  192       // x-projection block threads

typedef unsigned long long u64;

// Device scratch (sanctioned alternative to cudaMalloc)
__device__ __half g_xp[(size_t)BB * SSP * GG];   // x-projection + folded biases (fp16, ~202 MB)

// ---- packed f32x2 helpers (bit-exact fp32, 2 FMA per fma-pipe slot) ----
__device__ __forceinline__ u64 pack2(float lo, float hi) {
    u64 r; asm("mov.b64 %0, {%1, %2};" : "=l"(r) : "f"(lo), "f"(hi)); return r;
}
__device__ __forceinline__ void unpack2(u64 v, float& lo, float& hi) {
    asm("mov.b64 {%0, %1}, %2;" : "=f"(lo), "=f"(hi) : "l"(v));
}
__device__ __forceinline__ u64 fma2(u64 a, u64 b, u64 c) {
    u64 d; asm("fma.rn.f32x2 %0, %1, %2, %3;" : "=l"(d) : "l"(a), "l"(b), "l"(c)); return d;
}
__device__ __forceinline__ u64 add2(u64 a, u64 b) {
    u64 d; asm("add.rn.f32x2 %0, %1, %2;" : "=l"(d) : "l"(a), "l"(b)); return d;
}
__device__ __forceinline__ float tanh_fast(float x) {
    float t; asm("tanh.approx.f32 %0, %1;" : "=f"(t) : "f"(x)); return t;
}

// ---------------- Kernel 1: x-projection pre-pass (fp16 out, biases folded) ----------------
// For g<128 (z,r gates): xp = x.K + b_in[g] + b_rec[g]
// For g>=128 (h gate):   xp = x.K + b_in[g]            (b_rec stays in scan)
__global__ __launch_bounds__(NTP)
void xproj_kernel(const float* __restrict__ inputs,
                  const float* __restrict__ k_in,
                  const float* __restrict__ bias) {
    __shared__ __align__(16) float sx[XROWS * FIN];
    const int g  = threadIdx.x;
    const int bb = blockIdx.x / (SS / XROWS);        // batch
    const int s0 = (blockIdx.x % (SS / XROWS)) * XROWS;
    const size_t row0 = (size_t)bb * SS + s0;        // source row
    const size_t drow0 = (size_t)bb * SSP + s0;      // dest row (padded layout)

    u64 K2[8];
    #pragma unroll
    for (int f2 = 0; f2 < 8; f2++) {
        float lo = k_in[(2 * f2) * GG + g];
        float hi = (2 * f2 + 1 < 15) ? k_in[(2 * f2 + 1) * GG + g] : 0.0f;
        K2[f2] = pack2(lo, hi);
    }
    const float bfold = bias[g] + ((g < 128) ? bias[GG + g] : 0.0f);

    const float4* src = (const float4*)(inputs + row0 * FIN);
    for (int i = g; i < XROWS * 4; i += NTP) ((float4*)sx)[i] = src[i];
    __syncthreads();

    __half* dst = g_xp + drow0 * GG + g;
    #pragma unroll 4
    for (int r = 0; r < XROWS; r++) {
        const ulonglong2* xr = (const ulonglong2*)(sx + r * FIN);
        ulonglong2 xv0 = xr[0], xv1 = xr[1];
        u64 c0 = fma2(xv0.x, K2[0], 0ull);
        u64 c1 = fma2(xv0.y, K2[1], 0ull);
        c0 = fma2(xv1.x, K2[2], c0);
        c1 = fma2(xv1.y, K2[3], c1);
        ulonglong2 xv2 = xr[2], xv3 = xr[3];
        c0 = fma2(xv2.x, K2[4], c0);
        c1 = fma2(xv2.y, K2[5], c1);
        c0 = fma2(xv3.x, K2[6], c0);
        c1 = fma2(xv3.y, K2[7], c1);
        float lo, hi; unpack2(add2(c0, c1), lo, hi);
        dst[(size_t)r * GG] = __float2half(bfold + (lo + hi));
    }
}

// ---------------- Kernel 2: GRU scan — one thread per column triple ----------------
__global__ __launch_bounds__(HH, 4)
void gru_scan_kernel(const float* __restrict__ inputs,   // (B,S,16) - for delta mean
                     const float* __restrict__ r_in,     // (64,192)
                     const float* __restrict__ bias,     // (2,192)
                     const float* __restrict__ w1,       // (64,64)
                     const float* __restrict__ b1,       // (64)
                     const float* __restrict__ bn_gamma,
                     const float* __restrict__ bn_beta,
                     const float* __restrict__ bn_mean,
                     const float* __restrict__ bn_var,
                     const float* __restrict__ w2,       // (64,1)
                     const float* __restrict__ b2,       // (1)
                     const float* __restrict__ Tp,       // (1)
                     float* __restrict__ out)            // (B,1)
{
    __shared__ __align__(16) float sm_h[2][HH];   // double-buffered hidden state
    __shared__ float sm_e[HH];
    __shared__ float sm_r[HH];

    const int j = threadIdx.x;    // column triple 0..63
    const int b = blockIdx.x;     // batch

    // Recurrent weights for columns j (z), 64+j (r), 128+j (h); f32x2 pairs over k
    u64 Rz[32], Rr[32], Rh[32];
    #pragma unroll
    for (int k2 = 0; k2 < 32; k2++) {
        Rz[k2] = pack2(r_in[(2 * k2) * GG + j],        r_in[(2 * k2 + 1) * GG + j]);
        Rr[k2] = pack2(r_in[(2 * k2) * GG + 64 + j],   r_in[(2 * k2 + 1) * GG + 64 + j]);
        Rh[k2] = pack2(r_in[(2 * k2) * GG + 128 + j],  r_in[(2 * k2 + 1) * GG + 128 + j]);
    }
    const float brh = bias[GG + 128 + j];   // only h-gate recurrent bias remains

    sm_h[0][j] = 0.0f;

    const __half* xpp = g_xp + (size_t)b * SSP * GG;
    // prefetch x-projection for s=0,1 (biases folded at prepass)
    float xz0 = __half2float(xpp[j]);
    float xr0 = __half2float(xpp[64 + j]);
    float xh0 = __half2float(xpp[128 + j]);
    float xz1 = __half2float(xpp[GG + j]);
    float xr1 = __half2float(xpp[GG + 64 + j]);
    float xh1 = __half2float(xpp[GG + 128 + j]);
    __syncthreads();

    for (int s = 0; s < SS; s++) {
        const int p = s & 1;

        // prefetch s+2 (padded rows: no predicate needed)
        const __half* qp = xpp + (size_t)(s + 2) * GG;
        float xz2 = __half2float(qp[j]);
        float xr2 = __half2float(qp[64 + j]);
        float xh2 = __half2float(qp[128 + j]);

        // three recurrent dots, all in-thread (96 fma2, 6 chains of depth 16)
        const ulonglong2* h4 = (const ulonglong2*)sm_h[p];   // broadcast LDS.128
        u64 az0 = 0ull, az1 = 0ull, ar0 = 0ull, ar1 = 0ull, ah0 = 0ull, ah1 = 0ull;
        #pragma unroll
        for (int q2 = 0; q2 < 16; q2++) {
            ulonglong2 hv = h4[q2];
            az0 = fma2(hv.x, Rz[2 * q2],     az0);
            ar0 = fma2(hv.x, Rr[2 * q2],     ar0);
            ah0 = fma2(hv.x, Rh[2 * q2],     ah0);
            az1 = fma2(hv.y, Rz[2 * q2 + 1], az1);
            ar1 = fma2(hv.y, Rr[2 * q2 + 1], ar1);
            ah1 = fma2(hv.y, Rh[2 * q2 + 1], ah1);
        }
        float lo, hi;
        unpack2(add2(az0, az1), lo, hi);  const float az  = xz0 + (lo + hi);
        unpack2(add2(ar0, ar1), lo, hi);  const float ar_ = xr0 + (lo + hi);
        unpack2(add2(ah0, ah1), lo, hi);  const float rh_ = brh + (lo + hi);

        // gates via MUFU.TANH (sigmoid(x) = 0.5 + 0.5*tanh(x/2))
        const float z  = 0.5f + 0.5f * tanh_fast(0.5f * az);
        const float r  = 0.5f + 0.5f * tanh_fast(0.5f * ar_);
        const float hh = tanh_fast(xh0 + r * rh_);
        const float ho = sm_h[p][j];
        sm_h[p ^ 1][j] = z * (ho - hh) + hh;

        xz0 = xz1; xr0 = xr1; xh0 = xh1;
        xz1 = xz2; xr1 = xr2; xh1 = xh2;
        __syncthreads();   // the ONLY barrier per step
    }

    // final h is in buffer 0 (SS even)
    const float* hf = sm_h[0];

    // ---------- delta mean (folded from separate kernel; once per batch) ----------
    {
        float s = 0.0f;
        const float* dp = inputs + ((size_t)b * SS + (size_t)j * 16) * FIN + 15;
        #pragma unroll
        for (int i = 0; i < 16; i++) s += dp[(size_t)i * FIN];
        sm_r[j] = s;
    }
    __syncthreads();
    if (j < 16) sm_r[j] += sm_r[j + 16] + sm_r[j + 32] + sm_r[j + 48];
    __syncthreads();
    if (j < 4)  sm_r[j] += sm_r[j + 4] + sm_r[j + 8] + sm_r[j + 12];
    __syncthreads();
    const float db = Tp[0] * ((sm_r[0] + sm_r[1]) + (sm_r[2] + sm_r[3])) * (1.0f / (float)SS);

    // ---------- Epilogue: MLP head + BN ----------
    {
        float acc = b1[j];
        #pragma unroll 8
        for (int k = 0; k < HH; k++)
            acc += (hf[k] + db) * w1[k * HH + j];
        float hr = fmaxf(acc, 0.0f);
        float hb = (hr - bn_mean[j]) * rsqrtf(bn_var[j] + 1e-3f) * bn_gamma[j] + bn_beta[j];
        sm_e[j] = hb * w2[j];
    }
    __syncthreads();

    if (j == 0) {
        float acc = b2[0];
        #pragma unroll 8
        for (int k = 0; k < HH; k++) acc += sm_e[k];
        out[b] = acc;
    }
}

extern "C" void kernel_launch(void* const* d_in, const int* in_sizes, int n_in,
                              void* d_out, int out_size) {
    const float* inputs   = (const float*)d_in[0];
    const float* gk       = (const float*)d_in[1];
    const float* grk      = (const float*)d_in[2];
    const float* gbias    = (const float*)d_in[3];
    const float* w1       = (const float*)d_in[4];
    const float* b1       = (const float*)d_in[5];
    const float* bn_gamma = (const float*)d_in[6];
    const float* bn_beta  = (const float*)d_in[7];
    const float* bn_mean  = (const float*)d_in[8];
    const float* bn_var   = (const float*)d_in[9];
    const float* w2       = (const float*)d_in[10];
    const float* b2       = (const float*)d_in[11];
    const float* T        = (const float*)d_in[12];
    float* out = (float*)d_out;

    xproj_kernel<<<(BB * SS) / XROWS, NTP>>>(inputs, gk, gbias);
    gru_scan_kernel<<<BB, HH>>>(inputs, grk, gbias, w1, b1,
                                bn_gamma, bn_beta, bn_mean, bn_var,
                                w2, b2, T, out);
}